// round 1
// baseline (speedup 1.0000x reference)
#include <cuda_runtime.h>
#include <math.h>

#define Dg 500
#define Hg 500
#define Wg 40
#define NWORDS 312500          // 10,000,000 / 32
#define MAXV 40000
#define MAXP 32
#define NTOT 1280000           // MAXV*MAXP
#define NB_SCAN 611            // ceil(NWORDS/512)

// ---------------- static device scratch (no allocation allowed) ----------------
__device__ unsigned g_bitmap[NWORDS];
__device__ unsigned g_prefix[NWORDS];
__device__ unsigned g_bsum[NB_SCAN];
__device__ int      g_cnt[MAXV];
__device__ float4   g_vfeat[MAXV * MAXP];      // 20.5 MB
__device__ float    g_S1[64], g_SS1[64], g_S2[64], g_SS2[64];
__device__ float    g_a1[64], g_c1[64], g_a2[64], g_c2[64], g_zemp[64];
__device__ float    g_Ne;

// ---------------- helpers ----------------
__device__ __forceinline__ bool point_key(float4 p, int& key) {
    // match jnp: ((xyz - RANGE_MIN) / VOXEL_SIZE).astype(int32)  (trunc toward zero)
    float qx = __fdiv_rn(p.x + 50.0f, 0.2f);
    float qy = __fdiv_rn(p.y + 50.0f, 0.2f);
    float qz = __fdiv_rn(p.z + 3.0f, 0.2f);
    int ix = (int)qx, iy = (int)qy, iz = (int)qz;
    if (ix < 0 || ix >= Dg || iy < 0 || iy >= Hg || iz < 0 || iz >= Wg) return false;
    key = ix * (Hg * Wg) + iy * Wg + iz;
    return true;
}

// ---------------- kernels ----------------
__global__ void k_zero(float* out, int zero_coords) {
    int i = blockIdx.x * blockDim.x + threadIdx.x;
    if (i < NWORDS) g_bitmap[i] = 0u;
    if (i < MAXV) g_cnt[i] = 0;
    if (i < 64) { g_S1[i] = 0.f; g_SS1[i] = 0.f; g_S2[i] = 0.f; g_SS2[i] = 0.f; }
    if (zero_coords && i < MAXV * 4) out[MAXV * 128 + i] = 0.f;
}

__global__ void k_build(const float4* __restrict__ pts, int N) {
    int i = blockIdx.x * blockDim.x + threadIdx.x;
    if (i >= N) return;
    int key;
    if (!point_key(pts[i], key)) return;
    atomicOr(&g_bitmap[key >> 5], 1u << (key & 31));
}

__global__ void k_scan1() {
    __shared__ unsigned sh[512];
    int tid = threadIdx.x;
    int i = blockIdx.x * 512 + tid;
    unsigned v = (i < NWORDS) ? (unsigned)__popc(g_bitmap[i]) : 0u;
    sh[tid] = v; __syncthreads();
    for (int off = 1; off < 512; off <<= 1) {
        unsigned t = (tid >= off) ? sh[tid - off] : 0u;
        __syncthreads();
        sh[tid] += t;
        __syncthreads();
    }
    if (i < NWORDS) g_prefix[i] = sh[tid] - v;       // exclusive within block
    if (tid == 511) g_bsum[blockIdx.x] = sh[tid];    // block total
}

__global__ void k_scan2() {
    __shared__ unsigned sh[1024];
    int t = threadIdx.x;
    unsigned v = (t < NB_SCAN) ? g_bsum[t] : 0u;
    sh[t] = v; __syncthreads();
    for (int off = 1; off < 1024; off <<= 1) {
        unsigned x = (t >= off) ? sh[t - off] : 0u;
        __syncthreads();
        sh[t] += x;
        __syncthreads();
    }
    if (t < NB_SCAN) g_bsum[t] = sh[t] - v;          // exclusive
}

__global__ void k_scan3() {
    int i = blockIdx.x * blockDim.x + threadIdx.x;
    if (i < NWORDS) g_prefix[i] += g_bsum[i >> 9];
}

__global__ void k_coords(float* __restrict__ out, int write_coords) {
    if (!write_coords) return;
    int w = blockIdx.x * blockDim.x + threadIdx.x;
    if (w >= NWORDS) return;
    unsigned m = g_bitmap[w];
    if (!m) return;
    unsigned r = g_prefix[w];
    if (r >= MAXV) return;
    float* cbase = out + (size_t)MAXV * 128;
    while (m) {
        int b = __ffs(m) - 1; m &= (m - 1);
        if (r < MAXV) {
            int key = w * 32 + b;
            int z = key / (Hg * Wg);
            int rem = key % (Hg * Wg);
            int y = rem / Wg;
            int x = rem % Wg;
            float4 c4 = make_float4(0.f, (float)z, (float)y, (float)x);
            *(float4*)(cbase + (size_t)r * 4) = c4;
        }
        r++;
    }
}

__global__ void k_scatter(const float4* __restrict__ pts, int N) {
    int i = blockIdx.x * blockDim.x + threadIdx.x;
    if (i >= N) return;
    float4 p = pts[i];
    int key;
    if (!point_key(p, key)) return;
    int w = key >> 5, b = key & 31;
    unsigned bits = g_bitmap[w];
    unsigned vid = g_prefix[w] + (unsigned)__popc(bits & ((1u << b) - 1u));
    if (vid >= MAXV) return;
    int slot = atomicAdd(&g_cnt[vid], 1);
    if (slot < MAXP) g_vfeat[vid * MAXP + slot] = p;
}

// layer-1 sums (S1, SS1) over filled rows
__global__ void k_stats1(const float* __restrict__ W1, const float* __restrict__ b1) {
    __shared__ float sS[64], sSS[64];
    int tid = threadIdx.x, lane = tid & 31, w = tid >> 5;
    int gw = blockIdx.x * 8 + w;
    int stride = gridDim.x * 8;
    float w0a = __ldg(&W1[lane]),       w1a = __ldg(&W1[64 + lane]);
    float w2a = __ldg(&W1[128 + lane]), w3a = __ldg(&W1[192 + lane]);
    float w0b = __ldg(&W1[lane + 32]),       w1b = __ldg(&W1[64 + lane + 32]);
    float w2b = __ldg(&W1[128 + lane + 32]), w3b = __ldg(&W1[192 + lane + 32]);
    float bb0 = __ldg(&b1[lane]), bb1 = __ldg(&b1[lane + 32]);
    float s0 = 0.f, s1 = 0.f, q0 = 0.f, q1 = 0.f;
    for (int v = gw; v < MAXV; v += stride) {
        int n = min(g_cnt[v], MAXP);
        for (int s = 0; s < n; s++) {
            float4 p = g_vfeat[v * MAXP + s];
            float y0 = fmaf(p.w, w3a, fmaf(p.z, w2a, fmaf(p.y, w1a, fmaf(p.x, w0a, bb0))));
            float y1 = fmaf(p.w, w3b, fmaf(p.z, w2b, fmaf(p.y, w1b, fmaf(p.x, w0b, bb1))));
            s0 += y0; q0 += y0 * y0; s1 += y1; q1 += y1 * y1;
        }
    }
    if (tid < 64) { sS[tid] = 0.f; sSS[tid] = 0.f; }
    __syncthreads();
    atomicAdd(&sS[lane], s0);      atomicAdd(&sS[lane + 32], s1);
    atomicAdd(&sSS[lane], q0);     atomicAdd(&sSS[lane + 32], q1);
    __syncthreads();
    if (tid < 64) { atomicAdd(&g_S1[tid], sS[tid]); atomicAdd(&g_SS1[tid], sSS[tid]); }
}

// Nf reduction + layer-1 BN consts + empty-row constants for layer 2
__global__ void k_statsA(const float* __restrict__ b1, const float* __restrict__ g1,
                         const float* __restrict__ be1, const float* __restrict__ W2,
                         const float* __restrict__ b2) {
    __shared__ int red[1024];
    __shared__ float hemp[64];
    __shared__ float sNe;
    int tid = threadIdx.x;
    int acc = 0;
    for (int v = tid; v < MAXV; v += 1024) acc += min(g_cnt[v], MAXP);
    red[tid] = acc; __syncthreads();
    for (int o = 512; o > 0; o >>= 1) { if (tid < o) red[tid] += red[tid + o]; __syncthreads(); }
    if (tid == 0) { sNe = (float)(NTOT - red[0]); g_Ne = sNe; }
    __syncthreads();
    if (tid < 64) {
        int j = tid;
        float Ne = sNe;
        float bj = __ldg(&b1[j]);
        float mu = (g_S1[j] + Ne * bj) / (float)NTOT;
        float var = (g_SS1[j] + Ne * bj * bj) / (float)NTOT - mu * mu;
        float inv = rsqrtf(var + 1e-5f);
        float a = inv * __ldg(&g1[j]);
        float c = __ldg(&be1[j]) - mu * a;
        g_a1[j] = a; g_c1[j] = c;
        hemp[j] = fmaxf(fmaf(bj, a, c), 0.f);
    }
    __syncthreads();
    if (tid < 64) {
        int j = tid;
        float z = __ldg(&b2[j]);
        #pragma unroll 8
        for (int k = 0; k < 64; k++) z = fmaf(hemp[k], __ldg(&W2[k * 64 + j]), z);
        g_zemp[j] = z;
    }
}

// layer-2 sums (S2, SS2) over filled rows
__global__ void k_stats2(const float* __restrict__ W1, const float* __restrict__ b1,
                         const float* __restrict__ W2, const float* __restrict__ b2) {
    __shared__ float W2s[4096];
    __shared__ float hb[8][64];
    __shared__ float sS[64], sSS[64];
    int tid = threadIdx.x, lane = tid & 31, w = tid >> 5;
    for (int i = tid; i < 4096; i += 256) W2s[i] = __ldg(&W2[i]);
    if (tid < 64) { sS[tid] = 0.f; sSS[tid] = 0.f; }
    __syncthreads();
    float w0a = __ldg(&W1[lane]),       w1a = __ldg(&W1[64 + lane]);
    float w2a = __ldg(&W1[128 + lane]), w3a = __ldg(&W1[192 + lane]);
    float w0b = __ldg(&W1[lane + 32]),       w1b = __ldg(&W1[64 + lane + 32]);
    float w2b = __ldg(&W1[128 + lane + 32]), w3b = __ldg(&W1[192 + lane + 32]);
    float bb0 = __ldg(&b1[lane]), bb1 = __ldg(&b1[lane + 32]);
    float a0 = g_a1[lane], c0 = g_c1[lane];
    float a1_ = g_a1[lane + 32], c1_ = g_c1[lane + 32];
    float zb0 = __ldg(&b2[lane]), zb1 = __ldg(&b2[lane + 32]);
    float s0 = 0.f, s1 = 0.f, q0 = 0.f, q1 = 0.f;
    int gw = blockIdx.x * 8 + w;
    int stride = gridDim.x * 8;
    for (int v = gw; v < MAXV; v += stride) {
        int n = min(g_cnt[v], MAXP);
        for (int s = 0; s < n; s++) {
            float4 p = g_vfeat[v * MAXP + s];
            float y0 = fmaf(p.w, w3a, fmaf(p.z, w2a, fmaf(p.y, w1a, fmaf(p.x, w0a, bb0))));
            float y1 = fmaf(p.w, w3b, fmaf(p.z, w2b, fmaf(p.y, w1b, fmaf(p.x, w0b, bb1))));
            hb[w][lane] = fmaxf(fmaf(y0, a0, c0), 0.f);
            hb[w][lane + 32] = fmaxf(fmaf(y1, a1_, c1_), 0.f);
            __syncwarp();
            float z0 = zb0, z1 = zb1;
            #pragma unroll 8
            for (int k = 0; k < 64; k++) {
                float hk = hb[w][k];
                z0 = fmaf(hk, W2s[k * 64 + lane], z0);
                z1 = fmaf(hk, W2s[k * 64 + lane + 32], z1);
            }
            s0 += z0; q0 += z0 * z0; s1 += z1; q1 += z1 * z1;
            __syncwarp();
        }
    }
    atomicAdd(&sS[lane], s0);  atomicAdd(&sS[lane + 32], s1);
    atomicAdd(&sSS[lane], q0); atomicAdd(&sSS[lane + 32], q1);
    __syncthreads();
    if (tid < 64) { atomicAdd(&g_S2[tid], sS[tid]); atomicAdd(&g_SS2[tid], sSS[tid]); }
}

__global__ void k_statsB(const float* __restrict__ g2, const float* __restrict__ be2) {
    int j = threadIdx.x;
    if (j >= 64) return;
    float Ne = g_Ne;
    float ze = g_zemp[j];
    float mu = (g_S2[j] + Ne * ze) / (float)NTOT;
    float var = (g_SS2[j] + Ne * ze * ze) / (float)NTOT - mu * mu;
    float inv = rsqrtf(var + 1e-5f);
    float a = inv * __ldg(&g2[j]);
    float c = __ldg(&be2[j]) - mu * a;
    g_a2[j] = a; g_c2[j] = c;
}

// full MLP per filled point, max over points per voxel, write output
__global__ void k_final(const float* __restrict__ W1, const float* __restrict__ b1,
                        const float* __restrict__ W2, const float* __restrict__ b2,
                        const float* __restrict__ W3, const float* __restrict__ b3,
                        float* __restrict__ out) {
    __shared__ float W3s[64 * 128];   // 32 KB
    __shared__ float hb[8][64];
    int tid = threadIdx.x, lane = tid & 31, w = tid >> 5;
    for (int i = tid; i < 64 * 128; i += 256) W3s[i] = __ldg(&W3[i]);
    __syncthreads();
    float w0a = __ldg(&W1[lane]),       w1a = __ldg(&W1[64 + lane]);
    float w2a = __ldg(&W1[128 + lane]), w3a = __ldg(&W1[192 + lane]);
    float w0b = __ldg(&W1[lane + 32]),       w1b = __ldg(&W1[64 + lane + 32]);
    float w2b = __ldg(&W1[128 + lane + 32]), w3b = __ldg(&W1[192 + lane + 32]);
    float bb0 = __ldg(&b1[lane]), bb1 = __ldg(&b1[lane + 32]);
    float a0 = g_a1[lane], c0 = g_c1[lane];
    float a1_ = g_a1[lane + 32], c1_ = g_c1[lane + 32];
    float a20 = g_a2[lane], c20 = g_c2[lane];
    float a21 = g_a2[lane + 32], c21 = g_c2[lane + 32];
    float zb0 = __ldg(&b2[lane]), zb1 = __ldg(&b2[lane + 32]);
    float o0b = __ldg(&b3[lane]),      o1b = __ldg(&b3[lane + 32]);
    float o2b = __ldg(&b3[lane + 64]), o3b = __ldg(&b3[lane + 96]);
    int gw = blockIdx.x * 8 + w;
    int stride = gridDim.x * 8;
    for (int v = gw; v < MAXV; v += stride) {
        int n = min(g_cnt[v], MAXP);
        float m0 = -INFINITY, m1 = -INFINITY, m2 = -INFINITY, m3 = -INFINITY;
        for (int s = 0; s < n; s++) {
            float4 p = g_vfeat[v * MAXP + s];
            float y0 = fmaf(p.w, w3a, fmaf(p.z, w2a, fmaf(p.y, w1a, fmaf(p.x, w0a, bb0))));
            float y1 = fmaf(p.w, w3b, fmaf(p.z, w2b, fmaf(p.y, w1b, fmaf(p.x, w0b, bb1))));
            hb[w][lane] = fmaxf(fmaf(y0, a0, c0), 0.f);
            hb[w][lane + 32] = fmaxf(fmaf(y1, a1_, c1_), 0.f);
            __syncwarp();
            float z0 = zb0, z1 = zb1;
            #pragma unroll 8
            for (int k = 0; k < 64; k++) {
                float hk = hb[w][k];
                z0 = fmaf(hk, __ldg(&W2[k * 64 + lane]), z0);
                z1 = fmaf(hk, __ldg(&W2[k * 64 + lane + 32]), z1);
            }
            float h20 = fmaxf(fmaf(z0, a20, c20), 0.f);
            float h21 = fmaxf(fmaf(z1, a21, c21), 0.f);
            __syncwarp();
            hb[w][lane] = h20;
            hb[w][lane + 32] = h21;
            __syncwarp();
            float o0 = o0b, o1 = o1b, o2 = o2b, o3 = o3b;
            #pragma unroll 8
            for (int k = 0; k < 64; k++) {
                float hk = hb[w][k];
                o0 = fmaf(hk, W3s[k * 128 + lane], o0);
                o1 = fmaf(hk, W3s[k * 128 + lane + 32], o1);
                o2 = fmaf(hk, W3s[k * 128 + lane + 64], o2);
                o3 = fmaf(hk, W3s[k * 128 + lane + 96], o3);
            }
            m0 = fmaxf(m0, o0); m1 = fmaxf(m1, o1);
            m2 = fmaxf(m2, o2); m3 = fmaxf(m3, o3);
            __syncwarp();
        }
        float* ov = out + (size_t)v * 128;
        ov[lane] = m0; ov[lane + 32] = m1; ov[lane + 64] = m2; ov[lane + 96] = m3;
    }
}

// ---------------- host ----------------
extern "C" void kernel_launch(void* const* d_in, const int* in_sizes, int n_in,
                              void* d_out, int out_size) {
    const float* pts = (const float*)d_in[0];
    const float* W1 = (const float*)d_in[1];
    const float* b1 = (const float*)d_in[2];
    const float* g1 = (const float*)d_in[3];
    const float* be1 = (const float*)d_in[4];
    const float* W2 = (const float*)d_in[5];
    const float* b2 = (const float*)d_in[6];
    const float* g2 = (const float*)d_in[7];
    const float* be2 = (const float*)d_in[8];
    const float* W3 = (const float*)d_in[9];
    const float* b3 = (const float*)d_in[10];
    float* out = (float*)d_out;
    int N = in_sizes[0] / 4;
    int wc = (out_size >= MAXV * 128 + MAXV * 4) ? 1 : 0;

    k_zero<<<(NWORDS + 255) / 256, 256>>>(out, wc);
    k_build<<<(N + 255) / 256, 256>>>((const float4*)pts, N);
    k_scan1<<<NB_SCAN, 512>>>();
    k_scan2<<<1, 1024>>>();
    k_scan3<<<(NWORDS + 255) / 256, 256>>>();
    k_coords<<<(NWORDS + 255) / 256, 256>>>(out, wc);
    k_scatter<<<(N + 255) / 256, 256>>>((const float4*)pts, N);
    k_stats1<<<296, 256>>>(W1, b1);
    k_statsA<<<1, 1024>>>(b1, g1, be1, W2, b2);
    k_stats2<<<296, 256>>>(W1, b1, W2, b2);
    k_statsB<<<1, 64>>>(g2, be2);
    k_final<<<296, 256>>>(W1, b1, W2, b2, W3, b3, out);
}